// round 4
// baseline (speedup 1.0000x reference)
#include <cuda_runtime.h>
#include <math.h>

// Problem constants
#define DIN   256      // agent input dim
#define C6    192      // S*6 = 32*6
#define CAN   128      // canvas size
#define NT    50       // samples per curve
#define NPTS  (32*NT)  // 1600 curve points per image
#define HDIM  129      // center coords are in [0,128]
#define HROW  68       // u32 words per H row (129 u16 slots, padded to 16B multiple)
#define HPWORDS (HDIM*HROW)   // 8772 (multiple of 4)
#define GY_OFF  HPWORDS
#define GROW  64       // u32 words per Gy row (128 py slots packed)
#define GWORDS  (HDIM*GROW)   // 8256
#define SMEM_PAINT ((GY_OFF + GWORDS) * 4)   // 68112 B

// ---------------------------------------------------------------------------
// Kernel A: mu = x@W + b ; sample = sigmoid(mu); constant log_prob / entropy.
// 8 batch rows per block, 192 threads (one per output col), 256 blocks.
// ---------------------------------------------------------------------------
#define RPB 8

__global__ void __launch_bounds__(C6) agent_kernel(
    const float* __restrict__ x,
    const float* __restrict__ W,
    const float* __restrict__ bvec,
    float* __restrict__ out,   // full output buffer
    int B)
{
    __shared__ float xs[DIN * RPB];   // [k][r]

    const int j    = threadIdx.x;          // output column 0..191
    const int row0 = blockIdx.x * RPB;

    for (int idx = j; idx < RPB * DIN; idx += C6) {
        int r = idx >> 8;        // idx / 256
        int k = idx & 255;       // idx % 256
        xs[k * RPB + r] = x[(size_t)(row0 + r) * DIN + k];
    }
    __syncthreads();

    float bj = bvec[j];
    float acc[RPB];
#pragma unroll
    for (int r = 0; r < RPB; ++r) acc[r] = bj;

    const float* Wj = W + j;
#pragma unroll 8
    for (int k = 0; k < DIN; ++k) {
        float w = __ldg(&Wj[(size_t)k * C6]);
        float4 v0 = *(const float4*)&xs[k * RPB];       // broadcast
        float4 v1 = *(const float4*)&xs[k * RPB + 4];
        acc[0] = fmaf(v0.x, w, acc[0]);
        acc[1] = fmaf(v0.y, w, acc[1]);
        acc[2] = fmaf(v0.z, w, acc[2]);
        acc[3] = fmaf(v0.w, w, acc[3]);
        acc[4] = fmaf(v1.x, w, acc[4]);
        acc[5] = fmaf(v1.y, w, acc[5]);
        acc[6] = fmaf(v1.z, w, acc[6]);
        acc[7] = fmaf(v1.w, w, acc[7]);
    }

    // Output layout: [sketch B*128*128][log_prob B][entropy B][sample B*192]
    const size_t off_lp  = (size_t)B * (CAN * CAN);
    const size_t off_ent = off_lp + B;
    const size_t off_smp = off_ent + B;

    // log_prob / entropy are constants (raw == mu).
    const float logscale = logf(1e-4f);
    const float l2pi     = logf(6.2831855f);           // log(fl32(2*pi))
    const float lp  = 192.0f * (-logscale - 0.5f * l2pi);
    const float ent = 192.0f * (0.5f + 0.5f * l2pi + logscale);
    if (j < RPB) {
        out[off_lp  + row0 + j] = lp;
        out[off_ent + row0 + j] = ent;
    }

    float* smp = out + off_smp + (size_t)row0 * C6 + j;
#pragma unroll
    for (int r = 0; r < RPB; ++r)
        smp[r * C6] = 1.0f / (1.0f + expf(-acc[r]));
}

// ---------------------------------------------------------------------------
// Kernel B: paint. One block per batch image.
//  1) histogram rounded bezier centers into packed-u16 Hp[129][68 u32]
//  2) pass A (y-window): Gy[cx][py] packed u16, vectorized 4 outputs/chunk
//  3) pass B (x-window): register-rolling over px, inline clip arithmetic
// Edge weights from clipping:  p=0 -> {2,1} on centers {0,1};
//                              p=127 -> {1,2,3} on centers {126,127,128}.
// All packed-u16 sums bounded by 14400 < 65536: no carry across halves.
// ---------------------------------------------------------------------------
__global__ void __launch_bounds__(256) paint_kernel(
    const float* __restrict__ sample,   // [B, 192]
    float* __restrict__ sketch)         // [B, 128, 128]
{
    extern __shared__ uint4 sh16[];       // 16B-aligned base
    unsigned int* sh = (unsigned int*)sh16;
    unsigned int* Hp = sh;              // [129][68] u32 (u16 pairs along cy)
    unsigned int* Gy = sh + GY_OFF;     // [129][64] u32 (u16 pairs along py)
    __shared__ float prm[C6];

    const int b   = blockIdx.x;
    const int tid = threadIdx.x;

    // zero Hp with 16B stores
    {
        uint4 z = make_uint4(0u, 0u, 0u, 0u);
        uint4* hp4 = (uint4*)Hp;
        for (int i = tid; i < HPWORDS / 4; i += 256) hp4[i] = z;
    }
    if (tid < C6) prm[tid] = __fmul_rn(sample[(size_t)b * C6 + tid], 128.0f);
    __syncthreads();

    // ---- histogram of rounded curve centers ----
    const float dt = 1.0f / 49.0f;   // fl32((1-0)/(NT-1))
    for (int p = tid; p < NPTS; p += 256) {
        int s = p / NT;
        int i = p - s * NT;
        float t = (i == NT - 1) ? 1.0f : __fmul_rn((float)i, dt);
        float u = __fadd_rn(1.0f, -t);
        float uu  = __fmul_rn(u, u);
        float ut2 = __fmul_rn(__fmul_rn(2.0f, u), t);
        float tt  = __fmul_rn(t, t);
        const float* q = &prm[s * 6];
        float X = __fadd_rn(__fadd_rn(__fmul_rn(uu, q[0]), __fmul_rn(ut2, q[2])),
                            __fmul_rn(tt, q[4]));
        float Y = __fadd_rn(__fadd_rn(__fmul_rn(uu, q[1]), __fmul_rn(ut2, q[3])),
                            __fmul_rn(tt, q[5]));
        int cx = (int)rintf(X);
        int cy = (int)rintf(Y);
        cx = min(max(cx, 0), HDIM - 1);
        cy = min(max(cy, 0), HDIM - 1);
        atomicAdd(&Hp[cx * HROW + (cy >> 1)], 1u << ((cy & 1) * 16));
    }
    __syncthreads();

    // ---- pass A: y-window sums -> Gy, 4 packed outputs per chunk ----
    // 129 rows x 16 chunks of 4 words
    for (int cch = tid; cch < HDIM * 16; cch += 256) {
        int row = cch >> 4;
        int i0  = (cch & 15) << 2;     // 0,4,...,60
        const unsigned int* hr = Hp + row * HROW;
        uint4 w = *(const uint4*)&hr[i0];
        unsigned int prev = (i0 == 0) ? 0u : hr[i0 - 1];
        unsigned int next = hr[i0 + 4];            // i0=60 -> word 64 (h128|0)
        unsigned int wv[4] = {w.x, w.y, w.z, w.w};
        unsigned int og[4];
#pragma unroll
        for (int k = 0; k < 4; ++k) {
            int i = i0 + k;
            unsigned int p0 = wv[k];
            unsigned int pm = (i == 0) ? (p0 << 16) : (k == 0 ? prev : wv[k - 1]);
            unsigned int pp = (k == 3) ? next : wv[k + 1];
            unsigned int a  = __funnelshift_l(pm, p0, 16);   // (h[2i-1], h[2i])
            unsigned int c  = __funnelshift_l(p0, pp, 16);   // (h[2i+1], h[2i+2])
            unsigned int o  = a + p0 + c;
            if (i == 63) {
                // py=127 needs H126 + 2*H127 + 3*H128; a+b+c gave H126+H127+H128
                unsigned int h127 = p0 >> 16;
                unsigned int h128 = pp & 0xffffu;
                o += (h127 + 2u * h128) << 16;
            }
            og[k] = o;
        }
        *(uint4*)&Gy[row * GROW + i0] = make_uint4(og[0], og[1], og[2], og[3]);
    }
    __syncthreads();

    // ---- pass B: register-rolling x-window + inline clip + STG.128 ----
    // thread = (g, strip): g = column group (8 py), strip = 8 px rows
    float* dst = sketch + (size_t)b * (CAN * CAN);
    {
        const int g     = tid & 15;          // 0..15 -> py base 8g
        const int strip = tid >> 4;          // 0..15 -> px base 8*strip
        const int px0   = strip << 3;
        const unsigned int* gcol = Gy + (g << 2);

        uint4 ga, gb, gc;
        if (px0 == 0) {
            gb = *(const uint4*)&gcol[0];
            gc = *(const uint4*)&gcol[GROW];
            ga = gb;  // unused at px=0
        } else {
            ga = *(const uint4*)&gcol[(px0 - 1) * GROW];
            gb = *(const uint4*)&gcol[(px0    ) * GROW];
            gc = *(const uint4*)&gcol[(px0 + 1) * GROW];
        }

#pragma unroll
        for (int k = 0; k < 8; ++k) {
            int px = px0 + k;
            uint4 n4;
            if (px == 0) {
                n4.x = 2u * gb.x + gc.x;  n4.y = 2u * gb.y + gc.y;
                n4.z = 2u * gb.z + gc.z;  n4.w = 2u * gb.w + gc.w;
            } else if (px == CAN - 1) {
                n4.x = ga.x + 2u * gb.x + 3u * gc.x;
                n4.y = ga.y + 2u * gb.y + 3u * gc.y;
                n4.z = ga.z + 2u * gb.z + 3u * gc.z;
                n4.w = ga.w + 2u * gb.w + 3u * gc.w;
            } else {
                n4.x = ga.x + gb.x + gc.x;
                n4.y = ga.y + gb.y + gc.y;
                n4.z = ga.z + gb.z + gc.z;
                n4.w = ga.w + gb.w + gc.w;
            }

            unsigned int nn[8] = {
                n4.x & 0xffffu, n4.x >> 16, n4.y & 0xffffu, n4.y >> 16,
                n4.z & 0xffffu, n4.z >> 16, n4.w & 0xffffu, n4.w >> 16
            };
            float ov[8];
#pragma unroll
            for (int e = 0; e < 8; ++e) {
                unsigned int m = min(nn[e], 5u);   // clip saturates at n>=5
                float v = __fadd_rn(0.3f, __fmul_rn((float)m, -0.07f));
                ov[e] = fmaxf(v, 0.0f);
            }

            float* d = dst + px * CAN + (g << 3);
            ((float4*)d)[0] = make_float4(ov[0], ov[1], ov[2], ov[3]);
            ((float4*)d)[1] = make_float4(ov[4], ov[5], ov[6], ov[7]);

            // roll window
            ga = gb; gb = gc;
            if (k < 7) gc = *(const uint4*)&gcol[(px + 2) * GROW];
        }
    }
}

// ---------------------------------------------------------------------------
extern "C" void kernel_launch(void* const* d_in, const int* in_sizes, int n_in,
                              void* d_out, int out_size)
{
    const float* x    = (const float*)d_in[0];
    const float* W    = (const float*)d_in[1];
    const float* bv   = (const float*)d_in[2];
    float* out        = (float*)d_out;

    int B = in_sizes[0] / DIN;   // 2048

    cudaFuncSetAttribute(paint_kernel,
                         cudaFuncAttributeMaxDynamicSharedMemorySize,
                         SMEM_PAINT);

    agent_kernel<<<B / RPB, C6>>>(x, W, bv, out, B);

    const float* sample = out + (size_t)B * (CAN * CAN) + 2 * (size_t)B;
    paint_kernel<<<B, 256, SMEM_PAINT>>>(sample, out);
}

// round 5
// speedup vs baseline: 1.2406x; 1.2406x over previous
#include <cuda_runtime.h>
#include <math.h>

// Problem constants
#define DIN   256      // agent input dim
#define C6    192      // S*6 = 32*6
#define CAN   128      // canvas size
#define NT    50       // samples per curve
#define NPTS  (32*NT)  // 1600 curve points per image
#define HDIM  129      // center coords are in [0,128]
#define HROW  68       // u32 words per H row (129 u16 slots, padded to 16B multiple)
#define HPWORDS (HDIM*HROW)   // 8772 (multiple of 4)
#define SMEM_PAINT (HPWORDS * 4)   // 35088 B -> 6 blocks/SM

// ---------------------------------------------------------------------------
// Kernel A: mu = x@W + b ; sample = sigmoid(mu); constant log_prob / entropy.
// 4 batch rows per block, 192 threads (one per output col), 512 blocks.
// k-loop in chunks of 16: all 16 W loads issued before consumption (MLP=16).
// ---------------------------------------------------------------------------
#define RPB 4

__global__ void __launch_bounds__(C6) agent_kernel(
    const float* __restrict__ x,
    const float* __restrict__ W,
    const float* __restrict__ bvec,
    float* __restrict__ out,   // full output buffer
    int B)
{
    __shared__ float xs[DIN * RPB];   // [k][r]

    const int j    = threadIdx.x;          // output column 0..191
    const int row0 = blockIdx.x * RPB;

    for (int idx = j; idx < RPB * DIN; idx += C6) {
        int r = idx >> 8;        // idx / 256
        int k = idx & 255;       // idx % 256
        xs[k * RPB + r] = x[(size_t)(row0 + r) * DIN + k];
    }
    __syncthreads();

    float bj = bvec[j];
    float a0 = bj, a1 = bj, a2 = bj, a3 = bj;

    const float* Wj = W + j;
#pragma unroll 1
    for (int k0 = 0; k0 < DIN; k0 += 16) {
        float wv[16];
#pragma unroll
        for (int u = 0; u < 16; ++u)
            wv[u] = Wj[(size_t)(k0 + u) * C6];     // 16 LDGs in flight
#pragma unroll
        for (int u = 0; u < 16; ++u) {
            float4 v = *(const float4*)&xs[(k0 + u) * RPB];  // broadcast
            a0 = fmaf(v.x, wv[u], a0);
            a1 = fmaf(v.y, wv[u], a1);
            a2 = fmaf(v.z, wv[u], a2);
            a3 = fmaf(v.w, wv[u], a3);
        }
    }

    // Output layout: [sketch B*128*128][log_prob B][entropy B][sample B*192]
    const size_t off_lp  = (size_t)B * (CAN * CAN);
    const size_t off_ent = off_lp + B;
    const size_t off_smp = off_ent + B;

    // log_prob / entropy are constants (raw == mu).
    const float logscale = logf(1e-4f);
    const float l2pi     = logf(6.2831855f);           // log(fl32(2*pi))
    const float lp  = 192.0f * (-logscale - 0.5f * l2pi);
    const float ent = 192.0f * (0.5f + 0.5f * l2pi + logscale);
    if (j < RPB) {
        out[off_lp  + row0 + j] = lp;
        out[off_ent + row0 + j] = ent;
    }

    float* smp = out + off_smp + (size_t)row0 * C6 + j;
    smp[0 * C6] = 1.0f / (1.0f + expf(-a0));
    smp[1 * C6] = 1.0f / (1.0f + expf(-a1));
    smp[2 * C6] = 1.0f / (1.0f + expf(-a2));
    smp[3 * C6] = 1.0f / (1.0f + expf(-a3));
}

// ---------------------------------------------------------------------------
// Kernel B: paint. One block per batch image.
//  1) histogram rounded bezier centers into packed-u16 Hp[129][68 u32]
//  2) pass A (y-window): IN PLACE, one thread per row, rolling registers
//  3) pass B (x-window): register-rolling over px, inline clip arithmetic
// Edge weights from clipping:  p=0 -> {2,1} on centers {0,1};
//                              p=127 -> {1,2,3} on centers {126,127,128}.
// All packed-u16 sums bounded by 14400 < 65536: no carry across halves.
// Only ~35 KB smem -> 6 resident blocks/SM.
// ---------------------------------------------------------------------------
__global__ void __launch_bounds__(256) paint_kernel(
    const float* __restrict__ sample,   // [B, 192]
    float* __restrict__ sketch)         // [B, 128, 128]
{
    extern __shared__ uint4 sh16[];       // 16B-aligned base
    unsigned int* Hp = (unsigned int*)sh16;   // [129][68] u32
    __shared__ float prm[C6];

    const int b   = blockIdx.x;
    const int tid = threadIdx.x;

    // zero Hp with 16B stores
    {
        uint4 z = make_uint4(0u, 0u, 0u, 0u);
        uint4* hp4 = (uint4*)Hp;
        for (int i = tid; i < HPWORDS / 4; i += 256) hp4[i] = z;
    }
    if (tid < C6) prm[tid] = __fmul_rn(sample[(size_t)b * C6 + tid], 128.0f);
    __syncthreads();

    // ---- histogram of rounded curve centers ----
    const float dt = 1.0f / 49.0f;   // fl32((1-0)/(NT-1))
    for (int p = tid; p < NPTS; p += 256) {
        int s = p / NT;
        int i = p - s * NT;
        float t = (i == NT - 1) ? 1.0f : __fmul_rn((float)i, dt);
        float u = __fadd_rn(1.0f, -t);
        float uu  = __fmul_rn(u, u);
        float ut2 = __fmul_rn(__fmul_rn(2.0f, u), t);
        float tt  = __fmul_rn(t, t);
        const float* q = &prm[s * 6];
        float X = __fadd_rn(__fadd_rn(__fmul_rn(uu, q[0]), __fmul_rn(ut2, q[2])),
                            __fmul_rn(tt, q[4]));
        float Y = __fadd_rn(__fadd_rn(__fmul_rn(uu, q[1]), __fmul_rn(ut2, q[3])),
                            __fmul_rn(tt, q[5]));
        int cx = (int)rintf(X);
        int cy = (int)rintf(Y);
        cx = min(max(cx, 0), HDIM - 1);
        cy = min(max(cy, 0), HDIM - 1);
        atomicAdd(&Hp[cx * HROW + (cy >> 1)], 1u << ((cy & 1) * 16));
    }
    __syncthreads();

    // ---- pass A (in place): y-window sums, one thread per histogram row ----
    // Word w of a row holds (h[2w] low, h[2w+1] high). Output word i packs
    // py=2i (low) and py=2i+1 (high) window sums. Rolling registers keep the
    // original neighbor words so the in-row overwrite is race-free.
    if (tid < HDIM) {
        unsigned int* hr = Hp + tid * HROW;
        unsigned int prev = 0u;          // original word i-1
        unsigned int cur  = hr[0];
#pragma unroll 4
        for (int i = 0; i < 64; ++i) {
            unsigned int nxt = hr[i + 1];             // original (not yet written)
            unsigned int pm  = (i == 0) ? (cur << 16) : prev;
            unsigned int a   = __funnelshift_l(pm, cur, 16);  // (h[2i-1], h[2i])
            unsigned int c   = __funnelshift_l(cur, nxt, 16); // (h[2i+1], h[2i+2])
            unsigned int o   = a + cur + c;
            if (i == 63) {
                // py=127 needs H126 + 2*H127 + 3*H128; a+b+c gave H126+H127+H128
                unsigned int h127 = cur >> 16;
                unsigned int h128 = nxt & 0xffffu;
                o += (h127 + 2u * h128) << 16;
            }
            prev = cur;
            hr[i] = o;
            cur = nxt;
        }
    }
    __syncthreads();

    // ---- pass B: register-rolling x-window + inline clip + STG.128 ----
    // thread = (g, strip): g = column group (8 py), strip = 8 px rows
    float* dst = sketch + (size_t)b * (CAN * CAN);
    {
        const int g     = tid & 15;          // 0..15 -> py base 8g
        const int strip = tid >> 4;          // 0..15 -> px base 8*strip
        const int px0   = strip << 3;
        const unsigned int* gcol = Hp + (g << 2);

        uint4 ga, gb, gc;
        if (px0 == 0) {
            gb = *(const uint4*)&gcol[0];
            gc = *(const uint4*)&gcol[HROW];
            ga = gb;  // unused at px=0
        } else {
            ga = *(const uint4*)&gcol[(px0 - 1) * HROW];
            gb = *(const uint4*)&gcol[(px0    ) * HROW];
            gc = *(const uint4*)&gcol[(px0 + 1) * HROW];
        }

#pragma unroll
        for (int k = 0; k < 8; ++k) {
            int px = px0 + k;
            uint4 n4;
            if (px == 0) {
                n4.x = 2u * gb.x + gc.x;  n4.y = 2u * gb.y + gc.y;
                n4.z = 2u * gb.z + gc.z;  n4.w = 2u * gb.w + gc.w;
            } else if (px == CAN - 1) {
                n4.x = ga.x + 2u * gb.x + 3u * gc.x;
                n4.y = ga.y + 2u * gb.y + 3u * gc.y;
                n4.z = ga.z + 2u * gb.z + 3u * gc.z;
                n4.w = ga.w + 2u * gb.w + 3u * gc.w;
            } else {
                n4.x = ga.x + gb.x + gc.x;
                n4.y = ga.y + gb.y + gc.y;
                n4.z = ga.z + gb.z + gc.z;
                n4.w = ga.w + gb.w + gc.w;
            }

            unsigned int nn[8] = {
                n4.x & 0xffffu, n4.x >> 16, n4.y & 0xffffu, n4.y >> 16,
                n4.z & 0xffffu, n4.z >> 16, n4.w & 0xffffu, n4.w >> 16
            };
            float ov[8];
#pragma unroll
            for (int e = 0; e < 8; ++e) {
                unsigned int m = min(nn[e], 5u);   // clip saturates at n>=5
                float v = __fadd_rn(0.3f, __fmul_rn((float)m, -0.07f));
                ov[e] = fmaxf(v, 0.0f);
            }

            float* d = dst + px * CAN + (g << 3);
            ((float4*)d)[0] = make_float4(ov[0], ov[1], ov[2], ov[3]);
            ((float4*)d)[1] = make_float4(ov[4], ov[5], ov[6], ov[7]);

            // roll window
            ga = gb; gb = gc;
            if (k < 7) gc = *(const uint4*)&gcol[(px + 2) * HROW];
        }
    }
}

// ---------------------------------------------------------------------------
extern "C" void kernel_launch(void* const* d_in, const int* in_sizes, int n_in,
                              void* d_out, int out_size)
{
    const float* x    = (const float*)d_in[0];
    const float* W    = (const float*)d_in[1];
    const float* bv   = (const float*)d_in[2];
    float* out        = (float*)d_out;

    int B = in_sizes[0] / DIN;   // 2048

    cudaFuncSetAttribute(paint_kernel,
                         cudaFuncAttributeMaxDynamicSharedMemorySize,
                         SMEM_PAINT);

    agent_kernel<<<B / RPB, C6>>>(x, W, bv, out, B);

    const float* sample = out + (size_t)B * (CAN * CAN) + 2 * (size_t)B;
    paint_kernel<<<B, 256, SMEM_PAINT>>>(sample, out);
}

// round 6
// speedup vs baseline: 1.3296x; 1.0717x over previous
#include <cuda_runtime.h>
#include <math.h>

// Problem constants
#define DIN   256      // agent input dim
#define C6    192      // S*6 = 32*6
#define CAN   128      // canvas size
#define NT    50       // samples per curve
#define NPTS  (32*NT)  // 1600 curve points per image
#define HDIM  129      // center coords are in [0,128]
#define HROW  68       // u32 words per H row (129 u16 slots, padded to 16B multiple)
#define HPWORDS (HDIM*HROW)   // 8772 (multiple of 4)
#define SMEM_PAINT (HPWORDS * 4)   // 35088 B -> 6 blocks/SM

// ---------------------------------------------------------------------------
// f32x2 packed helpers (bit-identical per-lane IEEE fp32 FMA)
// ---------------------------------------------------------------------------
__device__ __forceinline__ void ffma2(unsigned long long& d,
                                      unsigned long long a,
                                      unsigned long long b) {
    asm("fma.rn.f32x2 %0, %1, %2, %0;" : "+l"(d) : "l"(a), "l"(b));
}
__device__ __forceinline__ unsigned long long pack2(float lo, float hi) {
    unsigned long long r;
    asm("mov.b64 %0, {%1, %2};" : "=l"(r) : "f"(lo), "f"(hi));
    return r;
}
__device__ __forceinline__ void unpack2(unsigned long long v, float& lo, float& hi) {
    asm("mov.b64 {%0, %1}, %2;" : "=f"(lo), "=f"(hi) : "l"(v));
}

// ---------------------------------------------------------------------------
// Kernel A: mu = x@W + b ; sample = sigmoid(mu); constant log_prob / entropy.
// 2 batch rows per block (packed f32x2 accumulator), 192 threads, 1024 blocks
// (~41 warps/SM). W is read via __ldg and stays L1-resident (192KB < 228KB),
// so after the first block per SM the k-loop LDGs are L1 hits.
// Per k: LDG + LDS.64 + pack + 1 FFMA2  (4 instr for 4 flops/lane-pair).
// ---------------------------------------------------------------------------
#define RPB 2

__global__ void __launch_bounds__(C6) agent_kernel(
    const float* __restrict__ x,
    const float* __restrict__ W,
    const float* __restrict__ bvec,
    float* __restrict__ out,   // full output buffer
    int B)
{
    __shared__ float xs[DIN * RPB];   // [k][r], r in {0,1}

    const int j    = threadIdx.x;          // output column 0..191
    const int row0 = blockIdx.x * RPB;

    for (int idx = j; idx < RPB * DIN; idx += C6) {
        int k = idx >> 1;
        int r = idx & 1;
        xs[idx] = x[(size_t)(row0 + r) * DIN + k];
    }
    __syncthreads();

    float bj = bvec[j];
    unsigned long long acc = pack2(bj, bj);

    const float* Wj = W + j;
#pragma unroll 1
    for (int k0 = 0; k0 < DIN; k0 += 16) {
        float wv[16];
#pragma unroll
        for (int u = 0; u < 16; ++u)
            wv[u] = __ldg(&Wj[(size_t)(k0 + u) * C6]);   // 16 LDGs in flight
#pragma unroll
        for (int u = 0; u < 16; ++u) {
            unsigned long long v = *(const unsigned long long*)&xs[(k0 + u) * RPB];
            ffma2(acc, v, pack2(wv[u], wv[u]));
        }
    }

    float a0, a1;
    unpack2(acc, a0, a1);

    // Output layout: [sketch B*128*128][log_prob B][entropy B][sample B*192]
    const size_t off_lp  = (size_t)B * (CAN * CAN);
    const size_t off_ent = off_lp + B;
    const size_t off_smp = off_ent + B;

    // log_prob / entropy are constants (raw == mu).
    const float logscale = logf(1e-4f);
    const float l2pi     = logf(6.2831855f);           // log(fl32(2*pi))
    const float lp  = 192.0f * (-logscale - 0.5f * l2pi);
    const float ent = 192.0f * (0.5f + 0.5f * l2pi + logscale);
    if (j < RPB) {
        out[off_lp  + row0 + j] = lp;
        out[off_ent + row0 + j] = ent;
    }

    float* smp = out + off_smp + (size_t)row0 * C6 + j;
    smp[0 * C6] = 1.0f / (1.0f + expf(-a0));
    smp[1 * C6] = 1.0f / (1.0f + expf(-a1));
}

// ---------------------------------------------------------------------------
// Kernel B: paint. One block per batch image.
//  1) histogram rounded bezier centers into packed-u16 Hp[129][68 u32]
//  2) pass A (y-window): IN PLACE, one WARP per row: contiguous conflict-free
//     LDS/STS, neighbor words via shuffles.
//  3) pass B (x-window): register-rolling over px, inline clip arithmetic
// Edge weights from clipping:  p=0 -> {2,1} on centers {0,1};
//                              p=127 -> {1,2,3} on centers {126,127,128}.
// All packed-u16 sums bounded by 14400 < 65536: no carry across halves.
// 35 KB smem -> 6 resident blocks/SM.
// ---------------------------------------------------------------------------
__global__ void __launch_bounds__(256) paint_kernel(
    const float* __restrict__ sample,   // [B, 192]
    float* __restrict__ sketch)         // [B, 128, 128]
{
    extern __shared__ uint4 sh16[];       // 16B-aligned base
    unsigned int* Hp = (unsigned int*)sh16;   // [129][68] u32
    __shared__ float prm[C6];

    const int b   = blockIdx.x;
    const int tid = threadIdx.x;

    // zero Hp with 16B stores
    {
        uint4 z = make_uint4(0u, 0u, 0u, 0u);
        uint4* hp4 = (uint4*)Hp;
        for (int i = tid; i < HPWORDS / 4; i += 256) hp4[i] = z;
    }
    if (tid < C6) prm[tid] = __fmul_rn(sample[(size_t)b * C6 + tid], 128.0f);
    __syncthreads();

    // ---- histogram of rounded curve centers ----
    const float dt = 1.0f / 49.0f;   // fl32((1-0)/(NT-1))
    for (int p = tid; p < NPTS; p += 256) {
        int s = p / NT;
        int i = p - s * NT;
        float t = (i == NT - 1) ? 1.0f : __fmul_rn((float)i, dt);
        float u = __fadd_rn(1.0f, -t);
        float uu  = __fmul_rn(u, u);
        float ut2 = __fmul_rn(__fmul_rn(2.0f, u), t);
        float tt  = __fmul_rn(t, t);
        const float* q = &prm[s * 6];
        float X = __fadd_rn(__fadd_rn(__fmul_rn(uu, q[0]), __fmul_rn(ut2, q[2])),
                            __fmul_rn(tt, q[4]));
        float Y = __fadd_rn(__fadd_rn(__fmul_rn(uu, q[1]), __fmul_rn(ut2, q[3])),
                            __fmul_rn(tt, q[5]));
        int cx = (int)rintf(X);
        int cy = (int)rintf(Y);
        cx = min(max(cx, 0), HDIM - 1);
        cy = min(max(cy, 0), HDIM - 1);
        atomicAdd(&Hp[cx * HROW + (cy >> 1)], 1u << ((cy & 1) * 16));
    }
    __syncthreads();

    // ---- pass A (in place): y-window sums, one WARP per row ----
    // Lane l holds original words l and l+32 (and broadcast word 64).
    // Output word i packs py=2i (low) and py=2i+1 (high) window sums.
    // All reads happen into registers/shuffles before the in-row writes.
    {
        const int warp = tid >> 5;
        const int lane = tid & 31;
        for (int row = warp; row < HDIM; row += 8) {
            unsigned int* hr = Hp + row * HROW;
            unsigned int r0 = hr[lane];        // words 0..31 (conflict-free)
            unsigned int r1 = hr[32 + lane];   // words 32..63
            unsigned int r2 = hr[64];          // word 64 (h128|0), broadcast

            unsigned int lm  = __shfl_up_sync(0xffffffffu, r0, 1);   // w[l-1]
            unsigned int l31 = __shfl_sync(0xffffffffu, r0, 31);     // w[31]
            unsigned int m0  = __shfl_sync(0xffffffffu, r1, 0);      // w[32]
            unsigned int rp  = __shfl_down_sync(0xffffffffu, r0, 1); // w[l+1]
            unsigned int lm1 = __shfl_up_sync(0xffffffffu, r1, 1);   // w[l+31]
            unsigned int rp1 = __shfl_down_sync(0xffffffffu, r1, 1); // w[l+33]

            unsigned int wm  = (lane == 0)  ? (r0 << 16) : lm;  // i==0: pm = p0<<16
            unsigned int wp  = (lane == 31) ? m0  : rp;
            unsigned int wm1 = (lane == 0)  ? l31 : lm1;
            unsigned int wp1 = (lane == 31) ? r2  : rp1;

            // output word i = lane
            unsigned int a0w = __funnelshift_l(wm, r0, 16);   // (h[2i-1], h[2i])
            unsigned int c0w = __funnelshift_l(r0, wp, 16);   // (h[2i+1], h[2i+2])
            unsigned int o0  = a0w + r0 + c0w;

            // output word i = lane + 32
            unsigned int a1w = __funnelshift_l(wm1, r1, 16);
            unsigned int c1w = __funnelshift_l(r1, wp1, 16);
            unsigned int o1  = a1w + r1 + c1w;
            if (lane == 31) {
                // py=127 needs H126 + 2*H127 + 3*H128; sum gave H126+H127+H128
                unsigned int h127 = r1 >> 16;
                unsigned int h128 = wp1 & 0xffffu;
                o1 += (h127 + 2u * h128) << 16;
            }

            hr[lane]      = o0;   // conflict-free contiguous stores
            hr[32 + lane] = o1;
        }
    }
    __syncthreads();

    // ---- pass B: register-rolling x-window + inline clip + STG.128 ----
    // thread = (g, strip): g = column group (8 py), strip = 8 px rows
    float* dst = sketch + (size_t)b * (CAN * CAN);
    {
        const int g     = tid & 15;          // 0..15 -> py base 8g
        const int strip = tid >> 4;          // 0..15 -> px base 8*strip
        const int px0   = strip << 3;
        const unsigned int* gcol = Hp + (g << 2);

        uint4 ga, gb, gc;
        if (px0 == 0) {
            gb = *(const uint4*)&gcol[0];
            gc = *(const uint4*)&gcol[HROW];
            ga = gb;  // unused at px=0
        } else {
            ga = *(const uint4*)&gcol[(px0 - 1) * HROW];
            gb = *(const uint4*)&gcol[(px0    ) * HROW];
            gc = *(const uint4*)&gcol[(px0 + 1) * HROW];
        }

#pragma unroll
        for (int k = 0; k < 8; ++k) {
            int px = px0 + k;
            uint4 n4;
            if (px == 0) {
                n4.x = 2u * gb.x + gc.x;  n4.y = 2u * gb.y + gc.y;
                n4.z = 2u * gb.z + gc.z;  n4.w = 2u * gb.w + gc.w;
            } else if (px == CAN - 1) {
                n4.x = ga.x + 2u * gb.x + 3u * gc.x;
                n4.y = ga.y + 2u * gb.y + 3u * gc.y;
                n4.z = ga.z + 2u * gb.z + 3u * gc.z;
                n4.w = ga.w + 2u * gb.w + 3u * gc.w;
            } else {
                n4.x = ga.x + gb.x + gc.x;
                n4.y = ga.y + gb.y + gc.y;
                n4.z = ga.z + gb.z + gc.z;
                n4.w = ga.w + gb.w + gc.w;
            }

            unsigned int nn[8] = {
                n4.x & 0xffffu, n4.x >> 16, n4.y & 0xffffu, n4.y >> 16,
                n4.z & 0xffffu, n4.z >> 16, n4.w & 0xffffu, n4.w >> 16
            };
            float ov[8];
#pragma unroll
            for (int e = 0; e < 8; ++e) {
                unsigned int m = min(nn[e], 5u);   // clip saturates at n>=5
                float v = __fadd_rn(0.3f, __fmul_rn((float)m, -0.07f));
                ov[e] = fmaxf(v, 0.0f);
            }

            float* d = dst + px * CAN + (g << 3);
            ((float4*)d)[0] = make_float4(ov[0], ov[1], ov[2], ov[3]);
            ((float4*)d)[1] = make_float4(ov[4], ov[5], ov[6], ov[7]);

            // roll window
            ga = gb; gb = gc;
            if (k < 7) gc = *(const uint4*)&gcol[(px + 2) * HROW];
        }
    }
}

// ---------------------------------------------------------------------------
extern "C" void kernel_launch(void* const* d_in, const int* in_sizes, int n_in,
                              void* d_out, int out_size)
{
    const float* x    = (const float*)d_in[0];
    const float* W    = (const float*)d_in[1];
    const float* bv   = (const float*)d_in[2];
    float* out        = (float*)d_out;

    int B = in_sizes[0] / DIN;   // 2048

    cudaFuncSetAttribute(paint_kernel,
                         cudaFuncAttributeMaxDynamicSharedMemorySize,
                         SMEM_PAINT);

    agent_kernel<<<B / RPB, C6>>>(x, W, bv, out, B);

    const float* sample = out + (size_t)B * (CAN * CAN) + 2 * (size_t)B;
    paint_kernel<<<B, 256, SMEM_PAINT>>>(sample, out);
}